// round 15
// baseline (speedup 1.0000x reference)
#include <cuda_runtime.h>
#include <cuda_fp16.h>
#include <cstdint>

#define NB   8192
#define NFLD 64
#define DDIM 128

// ---------------- device globals (no allocation allowed) ----------------
__device__ __align__(16) __half g_Sh [(size_t)NB * NFLD * NFLD];   // S fp16, 64 MB
__device__ __align__(16) __half g_Fh [(size_t)NB * NFLD * DDIM];   // fp16(F), 128 MB
__device__ __align__(16) __half g_Wth[(size_t)NFLD * DDIM * NFLD]; // Wt[i][d][j] fp16
__device__ __align__(16) __half g_Kwh[DDIM * DDIM];                // fp16 K_w[e][d]
__device__ __align__(16) __half g_Qwh[DDIM * DDIM];                // fp16 Q_w[e][d]

// ---------------- helpers ----------------
__device__ __forceinline__ uint32_t smem_u32(const void* p) {
    uint32_t a;
    asm("{ .reg .u64 t; cvta.to.shared.u64 t, %1; cvt.u32.u64 %0, t; }"
        : "=r"(a) : "l"(p));
    return a;
}
__device__ __forceinline__ unsigned pk(float a, float b) {
    __half2 h = __floats2half2_rn(a, b);
    return *reinterpret_cast<unsigned*>(&h);
}
__device__ __forceinline__ uint4 cvt8(float4 a, float4 b) {
    return make_uint4(pk(a.x, a.y), pk(a.z, a.w), pk(b.x, b.y), pk(b.z, b.w));
}
__device__ __forceinline__ void ldsm4(uint32_t* r, uint32_t addr) {
    asm volatile("ldmatrix.sync.aligned.m8n8.x4.shared.b16 {%0,%1,%2,%3}, [%4];"
                 : "=r"(r[0]), "=r"(r[1]), "=r"(r[2]), "=r"(r[3]) : "r"(addr));
}
__device__ __forceinline__ void mma16(float* c, const uint32_t* a, const uint32_t* b) {
    asm volatile("mma.sync.aligned.m16n8k16.row.col.f32.f16.f16.f32 "
                 "{%0,%1,%2,%3},{%4,%5,%6,%7},{%8,%9},{%0,%1,%2,%3};"
                 : "+f"(c[0]), "+f"(c[1]), "+f"(c[2]), "+f"(c[3])
                 : "r"(a[0]), "r"(a[1]), "r"(a[2]), "r"(a[3]), "r"(b[0]), "r"(b[1]));
}
__device__ __forceinline__ uint32_t lda(uint32_t base, int ld, int row0, int colh, int lane) {
    return base + 2u * (uint32_t)((row0 + (lane & 15)) * ld + colh + ((lane >> 4) << 3));
}
__device__ __forceinline__ uint32_t ldb(uint32_t base, int ld, int n0, int k0, int lane) {
    int row  = n0 + ((lane >> 4) << 3) + (lane & 7);
    int koff = ((lane >> 3) & 1) << 3;
    return base + 2u * (uint32_t)(row * ld + k0 + koff);
}
__device__ __forceinline__ void dumph(char* smb, int ld, int row, int col, const float* c) {
    *reinterpret_cast<unsigned*>(smb + 2 * (row * ld + col))       = pk(c[0], c[1]);
    *reinterpret_cast<unsigned*>(smb + 2 * ((row + 8) * ld + col)) = pk(c[2], c[3]);
}
// cp.async 16B global -> shared
__device__ __forceinline__ void cpa16(uint32_t saddr, const void* g) {
    asm volatile("cp.async.cg.shared.global [%0], [%1], 16;" :: "r"(saddr), "l"(g));
}
#define CPA_COMMIT() asm volatile("cp.async.commit_group;" ::: "memory")
#define CPA_WAIT(n)  asm volatile("cp.async.wait_group %0;" :: "n"(n) : "memory")

// ---------------- prep: fp16 weights + W transpose (d-quartered) ----------------
// grid 258: bid<256 -> (i = bid>>2, d-quarter = bid&3); bid 256 -> Kw; 257 -> Qw
__global__ void prep(const float* __restrict__ W, const float* __restrict__ Kw,
                     const float* __restrict__ Qw) {
    extern __shared__ __half th[];            // 64 x 36
    const int bid = blockIdx.x, tid = threadIdx.x;
    if (bid < 256) {
        const int i = bid >> 2, d0 = (bid & 3) * 32;
        const float4* W4 = reinterpret_cast<const float4*>(W) + (size_t)i * 2048 + (d0 >> 2);
        #pragma unroll
        for (int it = 0; it < 2; it++) {
            int x = tid + it * 256;            // 0..511 : j = x>>3, f4 = x&7
            int j = x >> 3, f4 = x & 7;
            float4 v = W4[j * 32 + f4];
            __half* p = th + j * 36 + f4 * 4;
            p[0] = __float2half_rn(v.x); p[1] = __float2half_rn(v.y);
            p[2] = __float2half_rn(v.z); p[3] = __float2half_rn(v.w);
        }
        __syncthreads();
        {
            int dl = tid >> 3, c8 = tid & 7;   // 32 d x 8 uint4
            __half tmp[8];
            #pragma unroll
            for (int t = 0; t < 8; t++) tmp[t] = th[(c8 * 8 + t) * 36 + dl];
            reinterpret_cast<uint4*>(g_Wth)[(size_t)i * 1024 + (d0 + dl) * 8 + c8] =
                *reinterpret_cast<uint4*>(tmp);
        }
    } else {
        const float* src = (bid == 256) ? Kw : Qw;
        __half2* dst = reinterpret_cast<__half2*>((bid == 256) ? g_Kwh : g_Qwh);
        #pragma unroll
        for (int it = 0; it < 16; it++) {
            int x = tid + it * 256;
            float4 v = reinterpret_cast<const float4*>(src)[x];
            dst[2 * x]     = __floats2half2_rn(v.x, v.y);
            dst[2 * x + 1] = __floats2half2_rn(v.z, v.w);
        }
    }
}

// ---------------- k1: per 2 batches — Kf = F2@Kw^T, S = diag(F2@Kf^T), store fp16(F) ----------------
// smem: smF [128][136] (F2), smB [128][136] (Kw; S-stage [128][72] later), smKf [128][136] (Kf)
#define K1_OFF_B  34816
#define K1_OFF_KF 69632
#define K1_SMEM   104448

__global__ void __launch_bounds__(256, 2) k1(const float* __restrict__ F) {
    extern __shared__ char sm[];
    char* smF  = sm;
    char* smB  = sm + K1_OFF_B;
    char* smKf = sm + K1_OFF_KF;
    const uint32_t ubF = smem_u32(smF), ubB = smem_u32(smB), ubKf = smem_u32(smKf);
    const int tid = threadIdx.x, wid = tid >> 5, lane = tid & 31;
    const int wm = wid >> 2, wn = wid & 3;
    const int r0 = lane >> 2, cO = 2 * (lane & 3);
    const int bp = blockIdx.x;

    // ---- prefetch Kw -> smB; stage F (f32 -> fp16) -> smF ----
    #pragma unroll
    for (int it = 0; it < 8; it++) {
        int x = tid + it * 256;                    // 0..2047 uint4
        uint32_t d = 2u * (uint32_t)((x >> 4) * 136 + (x & 15) * 8);
        cpa16(ubB + d, reinterpret_cast<const uint4*>(g_Kwh) + x);
    }
    CPA_COMMIT();
    {
        const float4* F4 = reinterpret_cast<const float4*>(F) + (size_t)bp * 4096;
        #pragma unroll
        for (int it = 0; it < 8; it++) {
            int x = tid + it * 256;
            int u = x >> 4, c8 = x & 15;
            float4 a = F4[u * 32 + c8 * 2], b = F4[u * 32 + c8 * 2 + 1];
            *reinterpret_cast<uint4*>(smF + 2 * (u * 136 + c8 * 8)) = cvt8(a, b);
        }
    }
    CPA_WAIT(0);
    __syncthreads();

    // ---- GEMM1: Kf = F2 @ Kw^T (128x128, K=128) ----
    float accK[4][4][4];
    #pragma unroll
    for (int mt = 0; mt < 4; mt++)
        #pragma unroll
        for (int nt = 0; nt < 4; nt++)
            #pragma unroll
            for (int q = 0; q < 4; q++) accK[mt][nt][q] = 0.f;
    #pragma unroll
    for (int ks = 0; ks < 8; ks++) {
        uint32_t a[4][4], bq[2][4];
        #pragma unroll
        for (int mt = 0; mt < 4; mt++)
            ldsm4(a[mt], lda(ubF, 136, wm * 64 + mt * 16, ks * 16, lane));
        #pragma unroll
        for (int bt = 0; bt < 2; bt++)
            ldsm4(bq[bt], ldb(ubB, 136, wn * 32 + bt * 16, ks * 16, lane));
        #pragma unroll
        for (int mt = 0; mt < 4; mt++)
            #pragma unroll
            for (int nt = 0; nt < 4; nt++)
                mma16(accK[mt][nt], a[mt], &bq[nt >> 1][(nt & 1) * 2]);
    }

    // ---- dump Kf -> smKf (fresh buffer: no pre-sync needed) ----
    #pragma unroll
    for (int mt = 0; mt < 4; mt++)
        #pragma unroll
        for (int nt = 0; nt < 4; nt++)
            dumph(smKf, 136, wm * 64 + mt * 16 + r0, wn * 32 + nt * 8 + cO, accK[mt][nt]);
    __syncthreads();                               // Kf visible; GEMM1 reads done

    // ---- store fp16(F) now: STGs drain during GEMM2 ----
    #pragma unroll
    for (int it = 0; it < 8; it++) {
        int x = tid + it * 256;                    // 0..2047 uint4
        uint4 v = *reinterpret_cast<const uint4*>(smF + 2 * ((x >> 4) * 136 + (x & 15) * 8));
        reinterpret_cast<uint4*>(g_Fh)[(size_t)bp * 2048 + x] = v;
    }

    // ---- GEMM2: S diag blocks (per batch 64x64, K=128), B = Kf in smKf ----
    float accS[2][4][4];
    #pragma unroll
    for (int mt = 0; mt < 2; mt++)
        #pragma unroll
        for (int nt = 0; nt < 4; nt++)
            #pragma unroll
            for (int q = 0; q < 4; q++) accS[mt][nt][q] = 0.f;
    const int h = wid >> 2, ww = wid & 3;
    const int m0  = h * 64 + (ww & 1) * 32;        // i rows (batch-stacked)
    const int n0j = h * 64 + (ww >> 1) * 32;       // Kf rows (batch-stacked)
    #pragma unroll
    for (int ks = 0; ks < 8; ks++) {
        uint32_t a2[2][4], b2[2][4];
        #pragma unroll
        for (int mt = 0; mt < 2; mt++)
            ldsm4(a2[mt], lda(ubF, 136, m0 + mt * 16, ks * 16, lane));
        #pragma unroll
        for (int bt = 0; bt < 2; bt++)
            ldsm4(b2[bt], ldb(ubKf, 136, n0j + bt * 16, ks * 16, lane));
        #pragma unroll
        for (int mt = 0; mt < 2; mt++)
            #pragma unroll
            for (int nt = 0; nt < 4; nt++)
                mma16(accS[mt][nt], a2[mt], &b2[nt >> 1][(nt & 1) * 2]);
    }

    // ---- dump S -> smB reused as [128][72] (Kw dead since GEMM1 + sync) ----
    #pragma unroll
    for (int mt = 0; mt < 2; mt++)
        #pragma unroll
        for (int nt = 0; nt < 4; nt++)
            dumph(smB, 72, m0 + mt * 16 + r0, (ww >> 1) * 32 + nt * 8 + cO, accS[mt][nt]);
    __syncthreads();

    // ---- bulk store S ----
    #pragma unroll
    for (int it = 0; it < 4; it++) {
        int x = tid + it * 256;                    // 0..1023 uint4
        int bt = x >> 9, rem = x & 511, i = rem >> 3, c8 = rem & 7;
        uint4 v = *reinterpret_cast<const uint4*>(smB + 2 * ((bt * 64 + i) * 72 + c8 * 8));
        reinterpret_cast<uint4*>(g_Sh)[(size_t)bp * 1024 + bt * 512 + i * 8 + c8] = v;
    }
}

// ---------------- k2: out[:,i,:] = S[:,i,:]@Wt[i] + Fh[:,i,:]@Qw^T ----------------
// smem: smS [128][72], smW [128][72], smFh [128][136], smQ [128][136]
#define K2_OFF_W 18432
#define K2_OFF_F 36864
#define K2_OFF_Q 71680
#define K2_SMEM  106496

__global__ void __launch_bounds__(256, 2) k2(float* __restrict__ out) {
    extern __shared__ char sm[];
    char* smS  = sm;
    char* smW  = sm + K2_OFF_W;
    char* smFh = sm + K2_OFF_F;
    char* smQ  = sm + K2_OFF_Q;
    const uint32_t ubS = smem_u32(smS), ubW = smem_u32(smW);
    const uint32_t ubFh = smem_u32(smFh), ubQ = smem_u32(smQ);
    const int tid = threadIdx.x, wid = tid >> 5, lane = tid & 31;
    const int wm = wid >> 2, wn = wid & 3;
    const int r0 = lane >> 2, cO = 2 * (lane & 3);
    const int i = blockIdx.y;
    const int b0 = blockIdx.x * 128;

    // ---- group 0: Fh rows + Qw (Phase B operands) ----
    #pragma unroll
    for (int it = 0; it < 8; it++) {
        int x = tid + it * 256;                    // 0..2047
        int u = x >> 4, c8 = x & 15;
        cpa16(ubFh + 2u * (uint32_t)(u * 136 + c8 * 8),
              reinterpret_cast<const uint4*>(g_Fh) + ((size_t)(b0 + u) * NFLD + i) * 16 + c8);
        cpa16(ubQ + 2u * (uint32_t)(u * 136 + c8 * 8),
              reinterpret_cast<const uint4*>(g_Qwh) + x);
    }
    CPA_COMMIT();
    // ---- group 1: S + Wt[i] (Phase A operands) ----
    #pragma unroll
    for (int it = 0; it < 4; it++) {
        int x = tid + it * 256;                    // 0..1023
        int u = x >> 3, c8 = x & 7;
        cpa16(ubS + 2u * (uint32_t)(u * 72 + c8 * 8),
              reinterpret_cast<const uint4*>(g_Sh) + ((size_t)(b0 + u) * NFLD + i) * 8 + c8);
        cpa16(ubW + 2u * (uint32_t)(u * 72 + c8 * 8),
              reinterpret_cast<const uint4*>(g_Wth) + (size_t)i * 1024 + x);
    }
    CPA_COMMIT();

    float acc[4][4][4];
    #pragma unroll
    for (int mt = 0; mt < 4; mt++)
        #pragma unroll
        for (int nt = 0; nt < 4; nt++)
            #pragma unroll
            for (int q = 0; q < 4; q++) acc[mt][nt][q] = 0.f;

    CPA_WAIT(1);                                   // group 0 resident
    __syncthreads();

    // ---- Phase B: Fh @ Qw^T  (K = 128) ----
    #pragma unroll
    for (int ks = 0; ks < 8; ks++) {
        uint32_t a[4][4], bq[2][4];
        #pragma unroll
        for (int mt = 0; mt < 4; mt++)
            ldsm4(a[mt], lda(ubFh, 136, wm * 64 + mt * 16, ks * 16, lane));
        #pragma unroll
        for (int bt = 0; bt < 2; bt++)
            ldsm4(bq[bt], ldb(ubQ, 136, wn * 32 + bt * 16, ks * 16, lane));
        #pragma unroll
        for (int mt = 0; mt < 4; mt++)
            #pragma unroll
            for (int nt = 0; nt < 4; nt++)
                mma16(acc[mt][nt], a[mt], &bq[nt >> 1][(nt & 1) * 2]);
    }

    CPA_WAIT(0);                                   // group 1 resident
    __syncthreads();

    // ---- Phase A: S @ Wt[i]  (K = 64) ----
    #pragma unroll
    for (int ks = 0; ks < 4; ks++) {
        uint32_t a[4][4], bq[2][4];
        #pragma unroll
        for (int mt = 0; mt < 4; mt++)
            ldsm4(a[mt], lda(ubS, 72, wm * 64 + mt * 16, ks * 16, lane));
        #pragma unroll
        for (int bt = 0; bt < 2; bt++)
            ldsm4(bq[bt], ldb(ubW, 72, wn * 32 + bt * 16, ks * 16, lane));
        #pragma unroll
        for (int mt = 0; mt < 4; mt++)
            #pragma unroll
            for (int nt = 0; nt < 4; nt++)
                mma16(acc[mt][nt], a[mt], &bq[nt >> 1][(nt & 1) * 2]);
    }

    // ---- direct global stores (8-float contiguous runs per lane-quad) ----
    #pragma unroll
    for (int mt = 0; mt < 4; mt++) {
        int row = wm * 64 + mt * 16 + r0;
        #pragma unroll
        for (int nt = 0; nt < 4; nt++) {
            int col = wn * 32 + nt * 8 + cO;
            float* o0 = out + ((size_t)(b0 + row) * NFLD + i) * DDIM + col;
            float* o1 = out + ((size_t)(b0 + row + 8) * NFLD + i) * DDIM + col;
            *reinterpret_cast<float2*>(o0) = make_float2(acc[mt][nt][0], acc[mt][nt][1]);
            *reinterpret_cast<float2*>(o1) = make_float2(acc[mt][nt][2], acc[mt][nt][3]);
        }
    }
}

// ---------------- launch ----------------
extern "C" void kernel_launch(void* const* d_in, const int* in_sizes, int n_in,
                              void* d_out, int out_size) {
    const float* F  = (const float*)d_in[0];
    const float* W  = (const float*)d_in[1];
    const float* Kw = (const float*)d_in[2];
    const float* Qw = (const float*)d_in[3];
    float* out = (float*)d_out;

    cudaFuncSetAttribute(k1, cudaFuncAttributeMaxDynamicSharedMemorySize, K1_SMEM);
    cudaFuncSetAttribute(k2, cudaFuncAttributeMaxDynamicSharedMemorySize, K2_SMEM);

    prep<<<258, 256, 4608>>>(W, Kw, Qw);
    k1<<<NB / 2, 256, K1_SMEM>>>(F);
    dim3 g2(NB / 128, NFLD);
    k2<<<g2, 256, K2_SMEM>>>(out);
}

// round 16
// speedup vs baseline: 1.0625x; 1.0625x over previous
#include <cuda_runtime.h>
#include <cuda_fp16.h>
#include <cstdint>

#define NB   8192
#define NFLD 64
#define DDIM 128

// ---------------- device globals (no allocation allowed) ----------------
__device__ __align__(16) __half g_Sh [(size_t)NB * NFLD * NFLD];   // S fp16, 64 MB
__device__ __align__(16) __half g_Fh [(size_t)NB * NFLD * DDIM];   // fp16(F), 128 MB
__device__ __align__(16) __half g_Wth[(size_t)NFLD * DDIM * NFLD]; // Wt[i][d][j] fp16
__device__ __align__(16) __half g_Kwh[DDIM * DDIM];                // fp16 K_w[e][d]
__device__ __align__(16) __half g_Qwh[DDIM * DDIM];                // fp16 Q_w[e][d]

// ---------------- helpers ----------------
__device__ __forceinline__ uint32_t smem_u32(const void* p) {
    uint32_t a;
    asm("{ .reg .u64 t; cvta.to.shared.u64 t, %1; cvt.u32.u64 %0, t; }"
        : "=r"(a) : "l"(p));
    return a;
}
__device__ __forceinline__ unsigned pk(float a, float b) {
    __half2 h = __floats2half2_rn(a, b);
    return *reinterpret_cast<unsigned*>(&h);
}
__device__ __forceinline__ uint4 cvt8(float4 a, float4 b) {
    return make_uint4(pk(a.x, a.y), pk(a.z, a.w), pk(b.x, b.y), pk(b.z, b.w));
}
__device__ __forceinline__ void ldsm4(uint32_t* r, uint32_t addr) {
    asm volatile("ldmatrix.sync.aligned.m8n8.x4.shared.b16 {%0,%1,%2,%3}, [%4];"
                 : "=r"(r[0]), "=r"(r[1]), "=r"(r[2]), "=r"(r[3]) : "r"(addr));
}
__device__ __forceinline__ void mma16(float* c, const uint32_t* a, const uint32_t* b) {
    asm volatile("mma.sync.aligned.m16n8k16.row.col.f32.f16.f16.f32 "
                 "{%0,%1,%2,%3},{%4,%5,%6,%7},{%8,%9},{%0,%1,%2,%3};"
                 : "+f"(c[0]), "+f"(c[1]), "+f"(c[2]), "+f"(c[3])
                 : "r"(a[0]), "r"(a[1]), "r"(a[2]), "r"(a[3]), "r"(b[0]), "r"(b[1]));
}
__device__ __forceinline__ uint32_t lda(uint32_t base, int ld, int row0, int colh, int lane) {
    return base + 2u * (uint32_t)((row0 + (lane & 15)) * ld + colh + ((lane >> 4) << 3));
}
__device__ __forceinline__ uint32_t ldb(uint32_t base, int ld, int n0, int k0, int lane) {
    int row  = n0 + ((lane >> 4) << 3) + (lane & 7);
    int koff = ((lane >> 3) & 1) << 3;
    return base + 2u * (uint32_t)(row * ld + k0 + koff);
}
__device__ __forceinline__ void dumph(char* smb, int ld, int row, int col, const float* c) {
    *reinterpret_cast<unsigned*>(smb + 2 * (row * ld + col))       = pk(c[0], c[1]);
    *reinterpret_cast<unsigned*>(smb + 2 * ((row + 8) * ld + col)) = pk(c[2], c[3]);
}
// cp.async 16B global -> shared
__device__ __forceinline__ void cpa16(uint32_t saddr, const void* g) {
    asm volatile("cp.async.cg.shared.global [%0], [%1], 16;" :: "r"(saddr), "l"(g));
}
#define CPA_COMMIT() asm volatile("cp.async.commit_group;" ::: "memory")
#define CPA_WAIT(n)  asm volatile("cp.async.wait_group %0;" :: "n"(n) : "memory")

// ---------------- prep: fp16 weights + W transpose ----------------
__global__ void prep(const float* __restrict__ W, const float* __restrict__ Kw,
                     const float* __restrict__ Qw) {
    extern __shared__ __half th[];            // 64 x 136
    const int bid = blockIdx.x, tid = threadIdx.x;
    if (bid < 64) {
        const float4* W4 = reinterpret_cast<const float4*>(W) + (size_t)bid * 2048;
        #pragma unroll
        for (int it = 0; it < 8; it++) {
            int x = tid + it * 256;
            float4 v = W4[x];
            int j = x >> 5, d4 = (x & 31) * 4;
            __half* p = th + j * 136 + d4;
            p[0] = __float2half_rn(v.x); p[1] = __float2half_rn(v.y);
            p[2] = __float2half_rn(v.z); p[3] = __float2half_rn(v.w);
        }
        __syncthreads();
        #pragma unroll
        for (int it = 0; it < 4; it++) {
            int x = tid + it * 256;
            int d = x >> 3, j0 = (x & 7) * 8;
            __half tmp[8];
            #pragma unroll
            for (int t = 0; t < 8; t++) tmp[t] = th[(j0 + t) * 136 + d];
            reinterpret_cast<uint4*>(g_Wth)[(size_t)bid * 1024 + x] =
                *reinterpret_cast<uint4*>(tmp);
        }
    } else {
        const float* src = (bid == 64) ? Kw : Qw;
        __half2* dst = reinterpret_cast<__half2*>((bid == 64) ? g_Kwh : g_Qwh);
        #pragma unroll
        for (int it = 0; it < 16; it++) {
            int x = tid + it * 256;
            float4 v = reinterpret_cast<const float4*>(src)[x];
            dst[2 * x]     = __floats2half2_rn(v.x, v.y);
            dst[2 * x + 1] = __floats2half2_rn(v.z, v.w);
        }
    }
}

// ---------------- k1: per 2 batches — Kf = F2@Kw^T, S = diag(F2@Kf^T), store fp16(F) ----------------
// smem: smF [128][136] fp16 (F2), smB [128][136] (Kw -> Kf), smSt [128][72] (S stage)
#define K1_OFF_B  34816
#define K1_OFF_ST 69632
#define K1_SMEM   88064

__global__ void __launch_bounds__(256, 2) k1(const float* __restrict__ F) {
    extern __shared__ char sm[];
    char* smF  = sm;
    char* smB  = sm + K1_OFF_B;
    char* smSt = sm + K1_OFF_ST;
    const uint32_t ubF = smem_u32(smF), ubB = smem_u32(smB);
    const int tid = threadIdx.x, wid = tid >> 5, lane = tid & 31;
    const int wm = wid >> 2, wn = wid & 3;
    const int r0 = lane >> 2, cO = 2 * (lane & 3);
    const int bp = blockIdx.x;

    // ---- prefetch Kw -> smB; stage F (f32 -> fp16) -> smF ----
    #pragma unroll
    for (int it = 0; it < 8; it++) {
        int x = tid + it * 256;                    // 0..2047 uint4
        uint32_t d = 2u * (uint32_t)((x >> 4) * 136 + (x & 15) * 8);
        cpa16(ubB + d, reinterpret_cast<const uint4*>(g_Kwh) + x);
    }
    CPA_COMMIT();
    {
        const float4* F4 = reinterpret_cast<const float4*>(F) + (size_t)bp * 4096;
        #pragma unroll
        for (int it = 0; it < 8; it++) {
            int x = tid + it * 256;
            int u = x >> 4, c8 = x & 15;
            float4 a = F4[u * 32 + c8 * 2], b = F4[u * 32 + c8 * 2 + 1];
            *reinterpret_cast<uint4*>(smF + 2 * (u * 136 + c8 * 8)) = cvt8(a, b);
        }
    }
    CPA_WAIT(0);
    __syncthreads();

    // ---- GEMM1: Kf = F2 @ Kw^T (128x128, K=128) ----
    float accK[4][4][4];
    #pragma unroll
    for (int mt = 0; mt < 4; mt++)
        #pragma unroll
        for (int nt = 0; nt < 4; nt++)
            #pragma unroll
            for (int q = 0; q < 4; q++) accK[mt][nt][q] = 0.f;
    #pragma unroll
    for (int ks = 0; ks < 8; ks++) {
        uint32_t a[4][4], bq[2][4];
        #pragma unroll
        for (int mt = 0; mt < 4; mt++)
            ldsm4(a[mt], lda(ubF, 136, wm * 64 + mt * 16, ks * 16, lane));
        #pragma unroll
        for (int bt = 0; bt < 2; bt++)
            ldsm4(bq[bt], ldb(ubB, 136, wn * 32 + bt * 16, ks * 16, lane));
        #pragma unroll
        for (int mt = 0; mt < 4; mt++)
            #pragma unroll
            for (int nt = 0; nt < 4; nt++)
                mma16(accK[mt][nt], a[mt], &bq[nt >> 1][(nt & 1) * 2]);
    }
    __syncthreads();                               // Kw reads done

    // ---- dump Kf -> smB (over Kw) ----
    #pragma unroll
    for (int mt = 0; mt < 4; mt++)
        #pragma unroll
        for (int nt = 0; nt < 4; nt++)
            dumph(smB, 136, wm * 64 + mt * 16 + r0, wn * 32 + nt * 8 + cO, accK[mt][nt]);
    __syncthreads();

    // ---- GEMM2: S diag blocks (per batch 64x64, K=128) ----
    float accS[2][4][4];
    #pragma unroll
    for (int mt = 0; mt < 2; mt++)
        #pragma unroll
        for (int nt = 0; nt < 4; nt++)
            #pragma unroll
            for (int q = 0; q < 4; q++) accS[mt][nt][q] = 0.f;
    const int h = wid >> 2, ww = wid & 3;
    const int m0  = h * 64 + (ww & 1) * 32;        // i rows (batch-stacked)
    const int n0j = h * 64 + (ww >> 1) * 32;       // Kf rows (batch-stacked)
    #pragma unroll
    for (int ks = 0; ks < 8; ks++) {
        uint32_t a2[2][4], b2[2][4];
        #pragma unroll
        for (int mt = 0; mt < 2; mt++)
            ldsm4(a2[mt], lda(ubF, 136, m0 + mt * 16, ks * 16, lane));
        #pragma unroll
        for (int bt = 0; bt < 2; bt++)
            ldsm4(b2[bt], ldb(ubB, 136, n0j + bt * 16, ks * 16, lane));
        #pragma unroll
        for (int mt = 0; mt < 2; mt++)
            #pragma unroll
            for (int nt = 0; nt < 4; nt++)
                mma16(accS[mt][nt], a2[mt], &b2[nt >> 1][(nt & 1) * 2]);
    }

    // ---- dump S -> smSt [128][72] (fresh region, no WAR hazard) ----
    #pragma unroll
    for (int mt = 0; mt < 2; mt++)
        #pragma unroll
        for (int nt = 0; nt < 4; nt++)
            dumph(smSt, 72, m0 + mt * 16 + r0, (ww >> 1) * 32 + nt * 8 + cO, accS[mt][nt]);
    __syncthreads();

    // ---- bulk store S (from smSt) and fp16(F) (from smF) ----
    #pragma unroll
    for (int it = 0; it < 4; it++) {
        int x = tid + it * 256;                    // 0..1023 uint4
        int bt = x >> 9, rem = x & 511, i = rem >> 3, c8 = rem & 7;
        uint4 v = *reinterpret_cast<const uint4*>(smSt + 2 * ((bt * 64 + i) * 72 + c8 * 8));
        reinterpret_cast<uint4*>(g_Sh)[(size_t)bp * 1024 + bt * 512 + i * 8 + c8] = v;
    }
    #pragma unroll
    for (int it = 0; it < 8; it++) {
        int x = tid + it * 256;                    // 0..2047 uint4
        uint4 v = *reinterpret_cast<const uint4*>(smF + 2 * ((x >> 4) * 136 + (x & 15) * 8));
        reinterpret_cast<uint4*>(g_Fh)[(size_t)bp * 2048 + x] = v;
    }
}

// ---------------- k2: out[:,i,:] = S[:,i,:]@Wt[i] + Fh[:,i,:]@Qw^T ----------------
// smem: smS [128][72], smW [128][72], smFh [128][136], smQ [128][136]
#define K2_OFF_W 18432
#define K2_OFF_F 36864
#define K2_OFF_Q 71680
#define K2_SMEM  106496

__global__ void __launch_bounds__(256, 2) k2(float* __restrict__ out) {
    extern __shared__ char sm[];
    char* smS  = sm;
    char* smW  = sm + K2_OFF_W;
    char* smFh = sm + K2_OFF_F;
    char* smQ  = sm + K2_OFF_Q;
    const uint32_t ubS = smem_u32(smS), ubW = smem_u32(smW);
    const uint32_t ubFh = smem_u32(smFh), ubQ = smem_u32(smQ);
    const int tid = threadIdx.x, wid = tid >> 5, lane = tid & 31;
    const int wm = wid >> 2, wn = wid & 3;
    const int r0 = lane >> 2, cO = 2 * (lane & 3);
    const int i = blockIdx.y;
    const int b0 = blockIdx.x * 128;

    // ---- group 0: S + Wt[i] (Phase A operands, small: lands first) ----
    #pragma unroll
    for (int it = 0; it < 4; it++) {
        int x = tid + it * 256;                    // 0..1023
        int u = x >> 3, c8 = x & 7;
        cpa16(ubS + 2u * (uint32_t)(u * 72 + c8 * 8),
              reinterpret_cast<const uint4*>(g_Sh) + ((size_t)(b0 + u) * NFLD + i) * 8 + c8);
        cpa16(ubW + 2u * (uint32_t)(u * 72 + c8 * 8),
              reinterpret_cast<const uint4*>(g_Wth) + (size_t)i * 1024 + x);
    }
    CPA_COMMIT();
    // ---- group 1: Fh rows + Qw (Phase B operands, big: overlaps Phase A) ----
    #pragma unroll
    for (int it = 0; it < 8; it++) {
        int x = tid + it * 256;                    // 0..2047
        int u = x >> 4, c8 = x & 15;
        cpa16(ubFh + 2u * (uint32_t)(u * 136 + c8 * 8),
              reinterpret_cast<const uint4*>(g_Fh) + ((size_t)(b0 + u) * NFLD + i) * 16 + c8);
        cpa16(ubQ + 2u * (uint32_t)(u * 136 + c8 * 8),
              reinterpret_cast<const uint4*>(g_Qwh) + x);
    }
    CPA_COMMIT();

    float acc[4][4][4];
    #pragma unroll
    for (int mt = 0; mt < 4; mt++)
        #pragma unroll
        for (int nt = 0; nt < 4; nt++)
            #pragma unroll
            for (int q = 0; q < 4; q++) acc[mt][nt][q] = 0.f;

    CPA_WAIT(1);                                   // S + W resident
    __syncthreads();

    // ---- Phase A: S @ Wt[i]  (K = 64) — overlaps Fh/Qw in flight ----
    #pragma unroll
    for (int ks = 0; ks < 4; ks++) {
        uint32_t a[4][4], bq[2][4];
        #pragma unroll
        for (int mt = 0; mt < 4; mt++)
            ldsm4(a[mt], lda(ubS, 72, wm * 64 + mt * 16, ks * 16, lane));
        #pragma unroll
        for (int bt = 0; bt < 2; bt++)
            ldsm4(bq[bt], ldb(ubW, 72, wn * 32 + bt * 16, ks * 16, lane));
        #pragma unroll
        for (int mt = 0; mt < 4; mt++)
            #pragma unroll
            for (int nt = 0; nt < 4; nt++)
                mma16(acc[mt][nt], a[mt], &bq[nt >> 1][(nt & 1) * 2]);
    }

    CPA_WAIT(0);                                   // Fh + Qw resident
    __syncthreads();

    // ---- Phase B: Fh @ Qw^T  (K = 128) ----
    #pragma unroll
    for (int ks = 0; ks < 8; ks++) {
        uint32_t a[4][4], bq[2][4];
        #pragma unroll
        for (int mt = 0; mt < 4; mt++)
            ldsm4(a[mt], lda(ubFh, 136, wm * 64 + mt * 16, ks * 16, lane));
        #pragma unroll
        for (int bt = 0; bt < 2; bt++)
            ldsm4(bq[bt], ldb(ubQ, 136, wn * 32 + bt * 16, ks * 16, lane));
        #pragma unroll
        for (int mt = 0; mt < 4; mt++)
            #pragma unroll
            for (int nt = 0; nt < 4; nt++)
                mma16(acc[mt][nt], a[mt], &bq[nt >> 1][(nt & 1) * 2]);
    }

    // ---- direct global stores (8-float contiguous runs per lane-quad) ----
    #pragma unroll
    for (int mt = 0; mt < 4; mt++) {
        int row = wm * 64 + mt * 16 + r0;
        #pragma unroll
        for (int nt = 0; nt < 4; nt++) {
            int col = wn * 32 + nt * 8 + cO;
            float* o0 = out + ((size_t)(b0 + row) * NFLD + i) * DDIM + col;
            float* o1 = out + ((size_t)(b0 + row + 8) * NFLD + i) * DDIM + col;
            *reinterpret_cast<float2*>(o0) = make_float2(acc[mt][nt][0], acc[mt][nt][1]);
            *reinterpret_cast<float2*>(o1) = make_float2(acc[mt][nt][2], acc[mt][nt][3]);
        }
    }
}

// ---------------- launch ----------------
extern "C" void kernel_launch(void* const* d_in, const int* in_sizes, int n_in,
                              void* d_out, int out_size) {
    const float* F  = (const float*)d_in[0];
    const float* W  = (const float*)d_in[1];
    const float* Kw = (const float*)d_in[2];
    const float* Qw = (const float*)d_in[3];
    float* out = (float*)d_out;

    cudaFuncSetAttribute(prep, cudaFuncAttributeMaxDynamicSharedMemorySize, 17408);
    cudaFuncSetAttribute(k1,   cudaFuncAttributeMaxDynamicSharedMemorySize, K1_SMEM);
    cudaFuncSetAttribute(k2,   cudaFuncAttributeMaxDynamicSharedMemorySize, K2_SMEM);

    prep<<<66, 256, 17408>>>(W, Kw, Qw);
    k1<<<NB / 2, 256, K1_SMEM>>>(F);
    dim3 g2(NB / 128, NFLD);
    k2<<<g2, 256, K2_SMEM>>>(out);
}

// round 17
// speedup vs baseline: 1.0715x; 1.0085x over previous
#include <cuda_runtime.h>
#include <cuda_fp16.h>
#include <cstdint>

#define NB   8192
#define NFLD 64
#define DDIM 128

// ---------------- device globals (no allocation allowed) ----------------
__device__ __align__(16) __half g_Sh [(size_t)NB * NFLD * NFLD];   // S fp16, 64 MB
__device__ __align__(16) __half g_Fh [(size_t)NB * NFLD * DDIM];   // fp16(F), 128 MB
__device__ __align__(16) __half g_Wth[(size_t)NFLD * DDIM * NFLD]; // Wt[i][d][j] fp16
__device__ __align__(16) __half g_Kwh[DDIM * DDIM];                // fp16 K_w[e][d]
__device__ __align__(16) __half g_Qwh[DDIM * DDIM];                // fp16 Q_w[e][d]

// ---------------- helpers ----------------
__device__ __forceinline__ uint32_t smem_u32(const void* p) {
    uint32_t a;
    asm("{ .reg .u64 t; cvta.to.shared.u64 t, %1; cvt.u32.u64 %0, t; }"
        : "=r"(a) : "l"(p));
    return a;
}
__device__ __forceinline__ unsigned pk(float a, float b) {
    __half2 h = __floats2half2_rn(a, b);
    return *reinterpret_cast<unsigned*>(&h);
}
__device__ __forceinline__ uint4 cvt8(float4 a, float4 b) {
    return make_uint4(pk(a.x, a.y), pk(a.z, a.w), pk(b.x, b.y), pk(b.z, b.w));
}
__device__ __forceinline__ void ldsm4(uint32_t* r, uint32_t addr) {
    asm volatile("ldmatrix.sync.aligned.m8n8.x4.shared.b16 {%0,%1,%2,%3}, [%4];"
                 : "=r"(r[0]), "=r"(r[1]), "=r"(r[2]), "=r"(r[3]) : "r"(addr));
}
__device__ __forceinline__ void mma16(float* c, const uint32_t* a, const uint32_t* b) {
    asm volatile("mma.sync.aligned.m16n8k16.row.col.f32.f16.f16.f32 "
                 "{%0,%1,%2,%3},{%4,%5,%6,%7},{%8,%9},{%0,%1,%2,%3};"
                 : "+f"(c[0]), "+f"(c[1]), "+f"(c[2]), "+f"(c[3])
                 : "r"(a[0]), "r"(a[1]), "r"(a[2]), "r"(a[3]), "r"(b[0]), "r"(b[1]));
}
__device__ __forceinline__ uint32_t lda(uint32_t base, int ld, int row0, int colh, int lane) {
    return base + 2u * (uint32_t)((row0 + (lane & 15)) * ld + colh + ((lane >> 4) << 3));
}
__device__ __forceinline__ uint32_t ldb(uint32_t base, int ld, int n0, int k0, int lane) {
    int row  = n0 + ((lane >> 4) << 3) + (lane & 7);
    int koff = ((lane >> 3) & 1) << 3;
    return base + 2u * (uint32_t)(row * ld + k0 + koff);
}
__device__ __forceinline__ void dumph(char* smb, int ld, int row, int col, const float* c) {
    *reinterpret_cast<unsigned*>(smb + 2 * (row * ld + col))       = pk(c[0], c[1]);
    *reinterpret_cast<unsigned*>(smb + 2 * ((row + 8) * ld + col)) = pk(c[2], c[3]);
}
// cp.async 16B global -> shared
__device__ __forceinline__ void cpa16(uint32_t saddr, const void* g) {
    asm volatile("cp.async.cg.shared.global [%0], [%1], 16;" :: "r"(saddr), "l"(g));
}
#define CPA_COMMIT() asm volatile("cp.async.commit_group;" ::: "memory")
#define CPA_WAIT(n)  asm volatile("cp.async.wait_group %0;" :: "n"(n) : "memory")

// ---------------- prep_kq: Kw/Qw fp16 conversion (must precede k1) ----------------
__global__ void prep_kq(const float* __restrict__ Kw, const float* __restrict__ Qw) {
    const int bid = blockIdx.x, tid = threadIdx.x;
    const float* src = (bid == 0) ? Kw : Qw;
    __half2* dst = reinterpret_cast<__half2*>((bid == 0) ? g_Kwh : g_Qwh);
    #pragma unroll
    for (int it = 0; it < 16; it++) {
        int x = tid + it * 256;
        float4 v = reinterpret_cast<const float4*>(src)[x];
        dst[2 * x]     = __floats2half2_rn(v.x, v.y);
        dst[2 * x + 1] = __floats2half2_rn(v.z, v.w);
    }
}

// ---------------- prep_w: W transpose (only k2 reads g_Wth; overlaps k1) ----------------
__global__ void prep_w(const float* __restrict__ W) {
    extern __shared__ __half th[];            // 64 x 136
    const int bid = blockIdx.x, tid = threadIdx.x;
    const float4* W4 = reinterpret_cast<const float4*>(W) + (size_t)bid * 2048;
    #pragma unroll
    for (int it = 0; it < 8; it++) {
        int x = tid + it * 256;
        float4 v = W4[x];
        int j = x >> 5, d4 = (x & 31) * 4;
        __half* p = th + j * 136 + d4;
        p[0] = __float2half_rn(v.x); p[1] = __float2half_rn(v.y);
        p[2] = __float2half_rn(v.z); p[3] = __float2half_rn(v.w);
    }
    __syncthreads();
    #pragma unroll
    for (int it = 0; it < 4; it++) {
        int x = tid + it * 256;
        int d = x >> 3, j0 = (x & 7) * 8;
        __half tmp[8];
        #pragma unroll
        for (int t = 0; t < 8; t++) tmp[t] = th[(j0 + t) * 136 + d];
        reinterpret_cast<uint4*>(g_Wth)[(size_t)bid * 1024 + x] =
            *reinterpret_cast<uint4*>(tmp);
    }
}

// ---------------- k1: per 2 batches — Kf = F2@Kw^T, S = diag(F2@Kf^T), store fp16(F) ----------------
// smem: smF [128][136] fp16 (F2), smB [128][136] (Kw -> Kf), smSt [128][72] (S stage)
#define K1_OFF_B  34816
#define K1_OFF_ST 69632
#define K1_SMEM   88064

__global__ void __launch_bounds__(256, 2) k1(const float* __restrict__ F) {
    extern __shared__ char sm[];
    char* smF  = sm;
    char* smB  = sm + K1_OFF_B;
    char* smSt = sm + K1_OFF_ST;
    const uint32_t ubF = smem_u32(smF), ubB = smem_u32(smB);
    const int tid = threadIdx.x, wid = tid >> 5, lane = tid & 31;
    const int wm = wid >> 2, wn = wid & 3;
    const int r0 = lane >> 2, cO = 2 * (lane & 3);
    const int bp = blockIdx.x;

    // ---- prefetch Kw -> smB; stage F (f32 -> fp16) -> smF ----
    #pragma unroll
    for (int it = 0; it < 8; it++) {
        int x = tid + it * 256;                    // 0..2047 uint4
        uint32_t d = 2u * (uint32_t)((x >> 4) * 136 + (x & 15) * 8);
        cpa16(ubB + d, reinterpret_cast<const uint4*>(g_Kwh) + x);
    }
    CPA_COMMIT();
    {
        const float4* F4 = reinterpret_cast<const float4*>(F) + (size_t)bp * 4096;
        #pragma unroll
        for (int it = 0; it < 8; it++) {
            int x = tid + it * 256;
            int u = x >> 4, c8 = x & 15;
            float4 a = F4[u * 32 + c8 * 2], b = F4[u * 32 + c8 * 2 + 1];
            *reinterpret_cast<uint4*>(smF + 2 * (u * 136 + c8 * 8)) = cvt8(a, b);
        }
    }
    CPA_WAIT(0);
    __syncthreads();

    // ---- GEMM1: Kf = F2 @ Kw^T (128x128, K=128) ----
    float accK[4][4][4];
    #pragma unroll
    for (int mt = 0; mt < 4; mt++)
        #pragma unroll
        for (int nt = 0; nt < 4; nt++)
            #pragma unroll
            for (int q = 0; q < 4; q++) accK[mt][nt][q] = 0.f;
    #pragma unroll
    for (int ks = 0; ks < 8; ks++) {
        uint32_t a[4][4], bq[2][4];
        #pragma unroll
        for (int mt = 0; mt < 4; mt++)
            ldsm4(a[mt], lda(ubF, 136, wm * 64 + mt * 16, ks * 16, lane));
        #pragma unroll
        for (int bt = 0; bt < 2; bt++)
            ldsm4(bq[bt], ldb(ubB, 136, wn * 32 + bt * 16, ks * 16, lane));
        #pragma unroll
        for (int mt = 0; mt < 4; mt++)
            #pragma unroll
            for (int nt = 0; nt < 4; nt++)
                mma16(accK[mt][nt], a[mt], &bq[nt >> 1][(nt & 1) * 2]);
    }

    // ---- store fp16(F) now: STGs drain during Kf dump + GEMM2 ----
    #pragma unroll
    for (int it = 0; it < 8; it++) {
        int x = tid + it * 256;                    // 0..2047 uint4
        uint4 v = *reinterpret_cast<const uint4*>(smF + 2 * ((x >> 4) * 136 + (x & 15) * 8));
        reinterpret_cast<uint4*>(g_Fh)[(size_t)bp * 2048 + x] = v;
    }
    __syncthreads();                               // Kw reads done

    // ---- dump Kf -> smB (over Kw) ----
    #pragma unroll
    for (int mt = 0; mt < 4; mt++)
        #pragma unroll
        for (int nt = 0; nt < 4; nt++)
            dumph(smB, 136, wm * 64 + mt * 16 + r0, wn * 32 + nt * 8 + cO, accK[mt][nt]);
    __syncthreads();

    // ---- GEMM2: S diag blocks (per batch 64x64, K=128) ----
    float accS[2][4][4];
    #pragma unroll
    for (int mt = 0; mt < 2; mt++)
        #pragma unroll
        for (int nt = 0; nt < 4; nt++)
            #pragma unroll
            for (int q = 0; q < 4; q++) accS[mt][nt][q] = 0.f;
    const int h = wid >> 2, ww = wid & 3;
    const int m0  = h * 64 + (ww & 1) * 32;        // i rows (batch-stacked)
    const int n0j = h * 64 + (ww >> 1) * 32;       // Kf rows (batch-stacked)
    #pragma unroll
    for (int ks = 0; ks < 8; ks++) {
        uint32_t a2[2][4], b2[2][4];
        #pragma unroll
        for (int mt = 0; mt < 2; mt++)
            ldsm4(a2[mt], lda(ubF, 136, m0 + mt * 16, ks * 16, lane));
        #pragma unroll
        for (int bt = 0; bt < 2; bt++)
            ldsm4(b2[bt], ldb(ubB, 136, n0j + bt * 16, ks * 16, lane));
        #pragma unroll
        for (int mt = 0; mt < 2; mt++)
            #pragma unroll
            for (int nt = 0; nt < 4; nt++)
                mma16(accS[mt][nt], a2[mt], &b2[nt >> 1][(nt & 1) * 2]);
    }

    // ---- dump S -> smSt [128][72] (fresh region, no WAR hazard) ----
    #pragma unroll
    for (int mt = 0; mt < 2; mt++)
        #pragma unroll
        for (int nt = 0; nt < 4; nt++)
            dumph(smSt, 72, m0 + mt * 16 + r0, (ww >> 1) * 32 + nt * 8 + cO, accS[mt][nt]);
    __syncthreads();

    // ---- bulk store S (from smSt) ----
    #pragma unroll
    for (int it = 0; it < 4; it++) {
        int x = tid + it * 256;                    // 0..1023 uint4
        int bt = x >> 9, rem = x & 511, i = rem >> 3, c8 = rem & 7;
        uint4 v = *reinterpret_cast<const uint4*>(smSt + 2 * ((bt * 64 + i) * 72 + c8 * 8));
        reinterpret_cast<uint4*>(g_Sh)[(size_t)bp * 1024 + bt * 512 + i * 8 + c8] = v;
    }
}

// ---------------- k2: out[:,i,:] = S[:,i,:]@Wt[i] + Fh[:,i,:]@Qw^T ----------------
// smem: smS [128][72], smW [128][72], smFh [128][136], smQ [128][136]
#define K2_OFF_W 18432
#define K2_OFF_F 36864
#define K2_OFF_Q 71680
#define K2_SMEM  106496

__global__ void __launch_bounds__(256, 2) k2(float* __restrict__ out) {
    extern __shared__ char sm[];
    char* smS  = sm;
    char* smW  = sm + K2_OFF_W;
    char* smFh = sm + K2_OFF_F;
    char* smQ  = sm + K2_OFF_Q;
    const uint32_t ubS = smem_u32(smS), ubW = smem_u32(smW);
    const uint32_t ubFh = smem_u32(smFh), ubQ = smem_u32(smQ);
    const int tid = threadIdx.x, wid = tid >> 5, lane = tid & 31;
    const int wm = wid >> 2, wn = wid & 3;
    const int r0 = lane >> 2, cO = 2 * (lane & 3);
    const int i = blockIdx.y;
    const int b0 = blockIdx.x * 128;

    // ---- group 0: S + Wt[i] (Phase A operands, small: lands first) ----
    #pragma unroll
    for (int it = 0; it < 4; it++) {
        int x = tid + it * 256;                    // 0..1023
        int u = x >> 3, c8 = x & 7;
        cpa16(ubS + 2u * (uint32_t)(u * 72 + c8 * 8),
              reinterpret_cast<const uint4*>(g_Sh) + ((size_t)(b0 + u) * NFLD + i) * 8 + c8);
        cpa16(ubW + 2u * (uint32_t)(u * 72 + c8 * 8),
              reinterpret_cast<const uint4*>(g_Wth) + (size_t)i * 1024 + x);
    }
    CPA_COMMIT();
    // ---- group 1: Fh rows + Qw (Phase B operands, big: overlaps Phase A) ----
    #pragma unroll
    for (int it = 0; it < 8; it++) {
        int x = tid + it * 256;                    // 0..2047
        int u = x >> 4, c8 = x & 15;
        cpa16(ubFh + 2u * (uint32_t)(u * 136 + c8 * 8),
              reinterpret_cast<const uint4*>(g_Fh) + ((size_t)(b0 + u) * NFLD + i) * 16 + c8);
        cpa16(ubQ + 2u * (uint32_t)(u * 136 + c8 * 8),
              reinterpret_cast<const uint4*>(g_Qwh) + x);
    }
    CPA_COMMIT();

    float acc[4][4][4];
    #pragma unroll
    for (int mt = 0; mt < 4; mt++)
        #pragma unroll
        for (int nt = 0; nt < 4; nt++)
            #pragma unroll
            for (int q = 0; q < 4; q++) acc[mt][nt][q] = 0.f;

    CPA_WAIT(1);                                   // S + W resident
    __syncthreads();

    // ---- Phase A: S @ Wt[i]  (K = 64) — overlaps Fh/Qw in flight ----
    #pragma unroll
    for (int ks = 0; ks < 4; ks++) {
        uint32_t a[4][4], bq[2][4];
        #pragma unroll
        for (int mt = 0; mt < 4; mt++)
            ldsm4(a[mt], lda(ubS, 72, wm * 64 + mt * 16, ks * 16, lane));
        #pragma unroll
        for (int bt = 0; bt < 2; bt++)
            ldsm4(bq[bt], ldb(ubW, 72, wn * 32 + bt * 16, ks * 16, lane));
        #pragma unroll
        for (int mt = 0; mt < 4; mt++)
            #pragma unroll
            for (int nt = 0; nt < 4; nt++)
                mma16(acc[mt][nt], a[mt], &bq[nt >> 1][(nt & 1) * 2]);
    }

    CPA_WAIT(0);                                   // Fh + Qw resident
    __syncthreads();

    // ---- Phase B: Fh @ Qw^T  (K = 128) ----
    #pragma unroll
    for (int ks = 0; ks < 8; ks++) {
        uint32_t a[4][4], bq[2][4];
        #pragma unroll
        for (int mt = 0; mt < 4; mt++)
            ldsm4(a[mt], lda(ubFh, 136, wm * 64 + mt * 16, ks * 16, lane));
        #pragma unroll
        for (int bt = 0; bt < 2; bt++)
            ldsm4(bq[bt], ldb(ubQ, 136, wn * 32 + bt * 16, ks * 16, lane));
        #pragma unroll
        for (int mt = 0; mt < 4; mt++)
            #pragma unroll
            for (int nt = 0; nt < 4; nt++)
                mma16(acc[mt][nt], a[mt], &bq[nt >> 1][(nt & 1) * 2]);
    }

    // ---- direct global stores (8-float contiguous runs per lane-quad) ----
    #pragma unroll
    for (int mt = 0; mt < 4; mt++) {
        int row = wm * 64 + mt * 16 + r0;
        #pragma unroll
        for (int nt = 0; nt < 4; nt++) {
            int col = wn * 32 + nt * 8 + cO;
            float* o0 = out + ((size_t)(b0 + row) * NFLD + i) * DDIM + col;
            float* o1 = out + ((size_t)(b0 + row + 8) * NFLD + i) * DDIM + col;
            *reinterpret_cast<float2*>(o0) = make_float2(acc[mt][nt][0], acc[mt][nt][1]);
            *reinterpret_cast<float2*>(o1) = make_float2(acc[mt][nt][2], acc[mt][nt][3]);
        }
    }
}

// ---------------- stream/event plumbing (static init: host objects only) ----------------
static cudaStream_t g_s2;
static cudaEvent_t  g_fork, g_join;
static cudaError_t  g_init_err = []() -> cudaError_t {
    cudaError_t e = cudaStreamCreateWithFlags(&g_s2, cudaStreamNonBlocking);
    if (e != cudaSuccess) return e;
    e = cudaEventCreateWithFlags(&g_fork, cudaEventDisableTiming);
    if (e != cudaSuccess) return e;
    return cudaEventCreateWithFlags(&g_join, cudaEventDisableTiming);
}();

// ---------------- launch ----------------
extern "C" void kernel_launch(void* const* d_in, const int* in_sizes, int n_in,
                              void* d_out, int out_size) {
    const float* F  = (const float*)d_in[0];
    const float* W  = (const float*)d_in[1];
    const float* Kw = (const float*)d_in[2];
    const float* Qw = (const float*)d_in[3];
    float* out = (float*)d_out;

    cudaFuncSetAttribute(prep_w, cudaFuncAttributeMaxDynamicSharedMemorySize, 17408);
    cudaFuncSetAttribute(k1,     cudaFuncAttributeMaxDynamicSharedMemorySize, K1_SMEM);
    cudaFuncSetAttribute(k2,     cudaFuncAttributeMaxDynamicSharedMemorySize, K2_SMEM);

    dim3 g2(NB / 128, NFLD);

    if (g_init_err == cudaSuccess) {
        // fork: W-transpose overlaps k1 (g_Wth only read by k2)
        cudaEventRecord(g_fork, 0);
        cudaStreamWaitEvent(g_s2, g_fork, 0);
        prep_w<<<64, 256, 17408, g_s2>>>(W);
        cudaEventRecord(g_join, g_s2);

        prep_kq<<<2, 256>>>(Kw, Qw);
        k1<<<NB / 2, 256, K1_SMEM>>>(F);

        cudaStreamWaitEvent(0, g_join, 0);         // g_Wth ready before k2
        k2<<<g2, 256, K2_SMEM>>>(out);
    } else {
        // fallback: sequential
        prep_w<<<64, 256, 17408>>>(W);
        prep_kq<<<2, 256>>>(Kw, Qw);
        k1<<<NB / 2, 256, K1_SMEM>>>(F);
        k2<<<g2, 256, K2_SMEM>>>(out);
    }
}